// round 17
// baseline (speedup 1.0000x reference)
#include <cuda_runtime.h>
#include <cuda_fp16.h>
#include <stdint.h>

#define DIM_I 128
#define DIM_G 16
#define DIM_O 128
#define NCHUNKS 64               // chunk = 2 input dims = 64 k-steps
#define A_BYTES 16384            // 128 rows x 64 fp16
#define B_BYTES 16384            // 128 o-rows x 64 fp16
#define STG_OFF 32768            // fp32 staging inside stage
#define ST_BYTES 65536           // A 16K | B 16K | staging 32K
#define NSTAGES 3
#define SM_PAR  (NSTAGES * ST_BYTES)         // 196608 ; bias|gamma|beta
#define SMEM_TOTAL (SM_PAR + 3 * 128 * 4)    // 198144
#define EPI_STRIDE 132

__device__ __forceinline__ uint32_t smem_u32(const void* p) {
    uint32_t a;
    asm("{ .reg .u64 t; cvta.to.shared.u64 t, %1; cvt.u32.u64 %0, t; }" : "=r"(a) : "l"(p));
    return a;
}
__device__ __forceinline__ void ldsm4(uint32_t& r0, uint32_t& r1, uint32_t& r2,
                                      uint32_t& r3, uint32_t a) {
    asm volatile("ldmatrix.sync.aligned.m8n8.x4.shared.b16 {%0,%1,%2,%3}, [%4];"
                 : "=r"(r0), "=r"(r1), "=r"(r2), "=r"(r3) : "r"(a));
}
__device__ __forceinline__ void mma16816(float* d, const uint32_t* a, const uint32_t* b) {
    asm volatile(
        "mma.sync.aligned.m16n8k16.row.col.f32.f16.f16.f32 "
        "{%0,%1,%2,%3}, {%4,%5,%6,%7}, {%8,%9}, {%0,%1,%2,%3};"
        : "+f"(d[0]), "+f"(d[1]), "+f"(d[2]), "+f"(d[3])
        : "r"(a[0]), "r"(a[1]), "r"(a[2]), "r"(a[3]), "r"(b[0]), "r"(b[1]));
}
#define CP_ASYNC16(dst, src) \
    asm volatile("cp.async.cg.shared.global [%0], [%1], 16;" :: "r"(dst), "l"(src) : "memory")
#define CP_COMMIT()    asm volatile("cp.async.commit_group;" ::: "memory")
#define CP_WAIT(n)     asm volatile("cp.async.wait_group %0;" :: "n"(n) : "memory")
// named barriers: full[s]=1..3, empty[s]=4..6, consumer epi=7
#define BAR_SYNC(id, cnt)   asm volatile("bar.sync %0, %1;"   :: "r"(id), "r"(cnt) : "memory")
#define BAR_ARRIVE(id, cnt) asm volatile("bar.arrive %0, %1;" :: "r"(id), "r"(cnt) : "memory")

// ---------------------------------------------------------------------------
// Single fused kernel. BM=128, 1 CTA/SM, warp-specialized, 3-stage ring.
// Threads 0-127 = consumers (4 warps, 64m x 64n, f32-acc mma.sync).
// Threads 128-255 = producers: trig-recurrence A features + cp.async of the
// RAW fp32 weights into smem staging, converted fp32->fp16 smem->smem one
// chunk behind the copy (deferred publish). No prep kernel, no global scratch.
// ---------------------------------------------------------------------------
__global__ __launch_bounds__(256, 1)
void fkan_ws(const float* __restrict__ X,
             const float* __restrict__ cosA,
             const float* __restrict__ sinA,
             const float* __restrict__ bias,
             const float* __restrict__ gamma,
             const float* __restrict__ beta,
             float* __restrict__ Out) {
    extern __shared__ unsigned char smem[];
    const uint32_t sb = smem_u32(smem);
    const int tid = threadIdx.x, w = tid >> 5, lane = tid & 31;
    const int n0blk = blockIdx.x * 128;

    if (tid < 128) {
        ((float*)(smem + SM_PAR))[tid]       = bias[tid];
        ((float*)(smem + SM_PAR))[128 + tid] = gamma[tid];
        ((float*)(smem + SM_PAR))[256 + tid] = beta[tid];
    }

    if (tid >= 128) {
        // ========== PRODUCER (threads 128..255; thread = row = o) ==========
        const int p = tid - 128;                     // 0..127
        uint32_t aoff[8];                            // [(dim&1)*4 + q], swizzled
        #pragma unroll
        for (int j = 0; j < 8; ++j)
            aoff[j] = (uint32_t)(p * 128 + ((j ^ (p & 7)) << 4));
        const float* xrow = X + (size_t)(n0blk + p) * DIM_I;
        const float* crow = cosA + (size_t)p * (DIM_I * DIM_G);
        const float* srow = sinA + (size_t)p * (DIM_I * DIM_G);

        // Convert staged fp32 weights of chunk cc into its fp16 B tile.
        // Staging per thread: floats [0..31]=cos(d0 g0-15, d1 g0-15),
        //                     [32..63]=sin. half2 = {cos, sin} per g.
        auto convertB = [&](int cc) {
            const int s2 = cc % NSTAGES;
            unsigned char* st2 = smem + s2 * ST_BYTES;
            const float* stag = (const float*)(st2 + STG_OFF + p * 256);
            unsigned char* bpl = st2 + A_BYTES;
            #pragma unroll
            for (int d = 0; d < 2; ++d)
                #pragma unroll
                for (int q = 0; q < 4; ++q) {
                    float4 cv = *(const float4*)(stag + d * 16 + q * 4);
                    float4 sv = *(const float4*)(stag + 32 + d * 16 + q * 4);
                    half2 h0 = __floats2half2_rn(cv.x, sv.x);
                    half2 h1 = __floats2half2_rn(cv.y, sv.y);
                    half2 h2 = __floats2half2_rn(cv.z, sv.z);
                    half2 h3 = __floats2half2_rn(cv.w, sv.w);
                    uint4 wv;
                    wv.x = *(uint32_t*)&h0; wv.y = *(uint32_t*)&h1;
                    wv.z = *(uint32_t*)&h2; wv.w = *(uint32_t*)&h3;
                    *(uint4*)(bpl + aoff[d * 4 + q]) = wv;
                }
        };

        float2 xq = *(const float2*)xrow;            // dims 0,1 (chunk 0)
        for (int pc = 0; pc < NCHUNKS; ++pc) {
            const int s = pc % NSTAGES;
            unsigned char* stgp = smem + s * ST_BYTES;
            const uint32_t stg = sb + (uint32_t)(s * ST_BYTES);
            if (pc >= NSTAGES) BAR_SYNC(4 + s, 256);         // wait empty[s]
            float2 xn;
            if (pc + 1 < NCHUNKS)
                xn = *(const float2*)(xrow + 2 * (pc + 1));  // prefetch X
            // ---- cp.async raw fp32 weights of THIS chunk into staging ----
            {
                const uint32_t dstc = stg + STG_OFF + (uint32_t)p * 256u;
                const char* csrc = (const char*)(crow + pc * 32);
                const char* ssrc = (const char*)(srow + pc * 32);
                #pragma unroll
                for (int j = 0; j < 8; ++j)
                    CP_ASYNC16(dstc + j * 16, csrc + j * 16);
                #pragma unroll
                for (int j = 0; j < 8; ++j)
                    CP_ASYNC16(dstc + 128 + j * 16, ssrc + j * 16);
                CP_COMMIT();
            }
            // ---- gen A: 2 dims for this row (k 0..31 and 32..63) ----
            #pragma unroll
            for (int hd = 0; hd < 2; ++hd) {
                float xv = hd ? xq.y : xq.x;
                float s1, c1;
                __sincosf(xv, &s1, &c1);
                uint32_t hv[16];
                float cg = c1, sg = s1;
                #pragma unroll
                for (int g = 0; g < 16; ++g) {
                    if (g) {
                        float cn = fmaf(cg, c1, -(sg * s1));
                        float sn = fmaf(sg, c1,  (cg * s1));
                        cg = cn; sg = sn;
                    }
                    half2 h = __floats2half2_rn(cg, sg);
                    hv[g] = *(uint32_t*)&h;
                }
                #pragma unroll
                for (int q = 0; q < 4; ++q)
                    *(uint4*)(stgp + aoff[hd * 4 + q]) =
                        make_uint4(hv[4*q], hv[4*q+1], hv[4*q+2], hv[4*q+3]);
            }
            // ---- deferred: chunk pc-1's staged fp32 has landed; convert
            //      and publish it (A stores of pc-1 done last iteration) ----
            if (pc >= 1) {
                CP_WAIT(1);
                convertB(pc - 1);
                BAR_ARRIVE(1 + ((pc - 1) % NSTAGES), 256);   // full[pc-1]
            }
            xq = xn;
        }
        CP_WAIT(0);
        convertB(NCHUNKS - 1);
        BAR_ARRIVE(1 + ((NCHUNKS - 1) % NSTAGES), 256);      // full[last]
        return;
    }

    // ====== CONSUMER (threads 0..127, 4 warps, 64m x 64n, f32-acc) =========
    const int mi = w & 1, ni = w >> 1;
    const int r8 = lane & 7, bsel = lane >> 3;
    const int kbA = bsel >> 1;
    const int mr0 = mi * 64 + r8 + ((bsel & 1) << 3);
    uint32_t moA[4];
    #pragma unroll
    for (int mt = 0; mt < 4; ++mt) moA[mt] = (uint32_t)((mr0 + 16 * mt) * 128);
    const int kbB = bsel & 1;
    const int nrb = ni * 64 + r8 + ((bsel >> 1) << 3);
    uint32_t noB[4];
    #pragma unroll
    for (int t = 0; t < 4; ++t) noB[t] = (uint32_t)((nrb + 16 * t) * 128);
    uint32_t kxA[4], kxB[4];
    #pragma unroll
    for (int ks = 0; ks < 4; ++ks) {
        kxA[ks] = (uint32_t)((((ks << 1) | kbA) ^ (mr0 & 7)) << 4);
        kxB[ks] = (uint32_t)((((ks << 1) | kbB) ^ (nrb & 7)) << 4);
    }

    float acc[4][8][4];
    #pragma unroll
    for (int mt = 0; mt < 4; ++mt)
        #pragma unroll
        for (int nt = 0; nt < 8; ++nt)
            #pragma unroll
            for (int j = 0; j < 4; ++j) acc[mt][nt][j] = 0.f;

    for (int c = 0; c < NCHUNKS; ++c) {
        const int s = c % NSTAGES;
        const uint32_t stg = sb + (uint32_t)(s * ST_BYTES);
        const uint32_t AH = stg, BP = stg + A_BYTES;
        BAR_SYNC(1 + s, 256);                        // wait full[s]
        uint32_t af[2][4][4], bf[2][16];
        // prime ks=0 operands
        #pragma unroll
        for (int mt = 0; mt < 4; ++mt)
            ldsm4(af[0][mt][0], af[0][mt][1], af[0][mt][2], af[0][mt][3],
                  AH + moA[mt] + kxA[0]);
        #pragma unroll
        for (int t = 0; t < 4; ++t)
            ldsm4(bf[0][4*t], bf[0][4*t+1], bf[0][4*t+2], bf[0][4*t+3],
                  BP + noB[t] + kxB[0]);
        #pragma unroll
        for (int ks = 0; ks < 4; ++ks) {
            const int cur = ks & 1, nxt = cur ^ 1;
            if (ks < 3) {                            // prefetch ks+1 operands
                #pragma unroll
                for (int mt = 0; mt < 4; ++mt)
                    ldsm4(af[nxt][mt][0], af[nxt][mt][1],
                          af[nxt][mt][2], af[nxt][mt][3],
                          AH + moA[mt] + kxA[ks + 1]);
                #pragma unroll
                for (int t = 0; t < 4; ++t)
                    ldsm4(bf[nxt][4*t], bf[nxt][4*t+1],
                          bf[nxt][4*t+2], bf[nxt][4*t+3],
                          BP + noB[t] + kxB[ks + 1]);
            }
            #pragma unroll
            for (int mt = 0; mt < 4; ++mt)
                #pragma unroll
                for (int nt = 0; nt < 8; ++nt) {
                    const uint32_t* b = &bf[cur][(nt >> 1) * 4 + (nt & 1) * 2];
                    mma16816(acc[mt][nt], af[cur][mt], b);
                }
        }
        BAR_ARRIVE(4 + s, 256);                      // empty[s]
    }

    // ---- epilogue: acc -> f32 smem tile ----
    {
        float* tile = (float*)smem;                  // 128 x 132 f32 = 67.6KB
        const int g4 = lane >> 2, t4 = lane & 3;
        #pragma unroll
        for (int mt = 0; mt < 4; ++mt)
            #pragma unroll
            for (int nt = 0; nt < 8; ++nt) {
                int rowm = mi * 64 + mt * 16 + g4;
                int col  = ni * 64 + nt * 8 + 2 * t4;
                *(float2*)&tile[rowm * EPI_STRIDE + col] =
                    make_float2(acc[mt][nt][0], acc[mt][nt][1]);
                *(float2*)&tile[(rowm + 8) * EPI_STRIDE + col] =
                    make_float2(acc[mt][nt][2], acc[mt][nt][3]);
            }
    }
    BAR_SYNC(7, 128);                                // consumers only

    // ---- two-pass LN: thread = row ----
    {
        const int r = tid;                           // 0..127
        const float* tile = (const float*)smem;
        const float* bS  = (const float*)(smem + SM_PAR);
        const float* gS  = bS + 128;
        const float* btS = bS + 256;
        float s = 0.f, q = 0.f;
        #pragma unroll
        for (int j4 = 0; j4 < 32; ++j4) {
            float4 t4v = *(const float4*)&tile[r * EPI_STRIDE + j4 * 4];
            float a0 = t4v.x + bS[j4*4+0], a1 = t4v.y + bS[j4*4+1];
            float a2 = t4v.z + bS[j4*4+2], a3 = t4v.w + bS[j4*4+3];
            s += (a0 + a1) + (a2 + a3);
            q += a0*a0 + a1*a1 + a2*a2 + a3*a3;
        }
        float mu  = s * (1.0f / 128.0f);
        float var = q * (1.0f / 128.0f) - mu * mu;
        float rs  = rsqrtf(var + 1e-5f);
        float4* op = (float4*)(Out + (size_t)(n0blk + r) * DIM_O);
        #pragma unroll
        for (int j4 = 0; j4 < 32; ++j4) {
            float4 t4v = *(const float4*)&tile[r * EPI_STRIDE + j4 * 4];
            float4 o;
            o.x = (t4v.x + bS[j4*4+0] - mu) * rs * gS[j4*4+0] + btS[j4*4+0];
            o.y = (t4v.y + bS[j4*4+1] - mu) * rs * gS[j4*4+1] + btS[j4*4+1];
            o.z = (t4v.z + bS[j4*4+2] - mu) * rs * gS[j4*4+2] + btS[j4*4+2];
            o.w = (t4v.w + bS[j4*4+3] - mu) * rs * gS[j4*4+3] + btS[j4*4+3];
            op[j4] = o;
        }
    }
}

// ---------------------------------------------------------------------------
extern "C" void kernel_launch(void* const* d_in, const int* in_sizes, int n_in,
                              void* d_out, int out_size) {
    const float* x     = (const float*)d_in[0];
    const float* cosA  = (const float*)d_in[1];
    const float* sinA  = (const float*)d_in[2];
    const float* bias  = (const float*)d_in[3];
    const float* gamma = (const float*)d_in[4];
    const float* beta  = (const float*)d_in[5];
    float* out = (float*)d_out;

    const int N = in_sizes[0] / DIM_I;

    cudaFuncSetAttribute(fkan_ws, cudaFuncAttributeMaxDynamicSharedMemorySize,
                         SMEM_TOTAL);

    fkan_ws<<<N / 128, 256, SMEM_TOTAL>>>(x, cosA, sinA, bias, gamma, beta, out);
}